// round 3
// baseline (speedup 1.0000x reference)
#include <cuda_runtime.h>
#include <math.h>

#define BATCH 4096
#define NNEG 64
#define DIM 128
#define HID 512
#define MARGINF 24.0f

#define MLP_ROWS 8                    // rows per MLP block
#define MLP_BLOCKS (BATCH / MLP_ROWS) // 512
#define NEG_BLOCKS BATCH              // 4096
#define GRID_TOTAL (MLP_BLOCKS + NEG_BLOCKS) // 4608; every 9th block is MLP

// Scratch (allocation-free rule: __device__ globals). Written non-atomically
// each launch -> graph-replay safe, no zeroing needed.
__device__ float g_conf[BATCH];
__device__ float g_dpos[BATCH];
__device__ float g_negsp[BATCH];   // sum over negs of softplus(d_neg - MARGIN)

__device__ __forceinline__ float warp_sum(float v) {
#pragma unroll
    for (int o = 16; o; o >>= 1) v += __shfl_xor_sync(0xffffffffu, v, o);
    return v;
}

// stable softplus(z) = max(z,0) + log1p(exp(-|z|));  -log_sigmoid(x) = softplus(-x)
__device__ __forceinline__ float softplusf(float z) {
    return fmaxf(z, 0.f) + log1pf(expf(-fabsf(z)));
}

// ---------------------------------------------------------------------------
// Fused kernel: block role by index. blockIdx.x % 9 == 8 -> MLP block
// (uniformly interleaved so every wave mixes DRAM-bound and FMA-bound work).
// ---------------------------------------------------------------------------
__global__ __launch_bounds__(256, 4) void fused_kernel(
    const int* __restrict__ pos, const int* __restrict__ negt,
    const float* __restrict__ ent, const float* __restrict__ rel,
    const float* __restrict__ W1, const float* __restrict__ b1,
    const float* __restrict__ W2, const float* __restrict__ b2)
{
    const int tid  = threadIdx.x;
    const int lane = tid & 31;
    const int wid  = tid >> 5;
    const int bI   = blockIdx.x;

    if ((bI % 9) == 8) {
        // =================== MLP / positive path ===========================
        const int mb   = bI / 9;            // 0..511
        const int row0 = mb * MLP_ROWS;

        __shared__ float shA[DIM][12];      // [k][row], 8 rows padded to 12
        __shared__ int   sh_idx[MLP_ROWS][3];
        __shared__ float sh_part[MLP_ROWS][2];

        if (tid < MLP_ROWS * 3)
            sh_idx[tid / 3][tid % 3] = pos[(row0 + tid / 3) * 3 + (tid % 3)];
        __syncthreads();

        // gather + diff (coalesced over k)
#pragma unroll
        for (int s = tid; s < MLP_ROWS * DIM; s += 256) {
            int row = s >> 7, k = s & 127;
            size_t h = (size_t)sh_idx[row][0];
            int    r = sh_idx[row][1];
            size_t t = (size_t)sh_idx[row][2];
            shA[k][row] = ent[h * DIM + k] + rel[(size_t)r * DIM + k] - ent[t * DIM + k];
        }
        __syncthreads();

        // d_pos: warp w -> row w
        {
            float s = 0.f;
#pragma unroll
            for (int kk = 0; kk < 4; kk++) s += fabsf(shA[lane + kk * 32][wid]);
            s = warp_sum(s);
            if (lane == 0) g_dpos[row0 + wid] = s;
        }

        // register-tiled GEMM: 2 rows x 8 cols per thread
        const int rg = tid >> 6;            // 0..3  -> rows rg*2, rg*2+1
        const int cg = tid & 63;            // 0..63 -> cols cg*8..cg*8+7
        float acc[2][8];
#pragma unroll
        for (int r = 0; r < 2; r++)
#pragma unroll
            for (int c = 0; c < 8; c++) acc[r][c] = 0.f;

        const float4* W1v = (const float4*)W1;   // row k = 128 float4

#pragma unroll 4
        for (int k = 0; k < DIM; k++) {
            float2 a2 = *(const float2*)&shA[k][rg * 2];
            float4 w0 = __ldg(&W1v[(size_t)k * (HID / 4) + cg * 2]);
            float4 w1 = __ldg(&W1v[(size_t)k * (HID / 4) + cg * 2 + 1]);
            float wv[8] = {w0.x, w0.y, w0.z, w0.w, w1.x, w1.y, w1.z, w1.w};
#pragma unroll
            for (int c = 0; c < 8; c++) {
                acc[0][c] = fmaf(a2.x, wv[c], acc[0][c]);
                acc[1][c] = fmaf(a2.y, wv[c], acc[1][c]);
            }
        }

        // epilogue: relu(acc + b1) * W2, partial-reduce across col groups
        float4 bv0 = __ldg((const float4*)(b1 + cg * 8));
        float4 bv1 = __ldg((const float4*)(b1 + cg * 8 + 4));
        float4 w20 = __ldg((const float4*)(W2 + cg * 8));
        float4 w21 = __ldg((const float4*)(W2 + cg * 8 + 4));
        float bv[8]  = {bv0.x, bv0.y, bv0.z, bv0.w, bv1.x, bv1.y, bv1.z, bv1.w};
        float w2v[8] = {w20.x, w20.y, w20.z, w20.w, w21.x, w21.y, w21.z, w21.w};

        const int half = (cg >= 32);
#pragma unroll
        for (int r = 0; r < 2; r++) {
            float s = 0.f;
#pragma unroll
            for (int c = 0; c < 8; c++)
                s += fmaxf(acc[r][c] + bv[c], 0.f) * w2v[c];
            s = warp_sum(s);
            if (lane == 0) sh_part[rg * 2 + r][half] = s;
        }
        __syncthreads();
        if (tid < MLP_ROWS) {
            float s = b2[0] + sh_part[tid][0] + sh_part[tid][1];
            g_conf[row0 + tid] = 1.f / (1.f + expf(-s));
        }
    } else {
        // =================== negative path =================================
        const int b = bI - bI / 9;          // 0..4095 (skip MLP slots)
        __shared__ float sh[8];

        float local = 0.f;
#pragma unroll
        for (int n = wid; n < NNEG; n += 8) {
            int base = (b * NNEG + n) * 3;
            int hi = __ldg(negt + base);
            int ri = __ldg(negt + base + 1);
            int ti = __ldg(negt + base + 2);
            float4 a  = __ldg((const float4*)(ent + (size_t)hi * DIM) + lane);
            float4 rr = __ldg((const float4*)(rel + (size_t)ri * DIM) + lane);
            float4 c  = __ldg((const float4*)(ent + (size_t)ti * DIM) + lane);
            float s = fabsf(a.x + rr.x - c.x) + fabsf(a.y + rr.y - c.y)
                    + fabsf(a.z + rr.z - c.z) + fabsf(a.w + rr.w - c.w);
            s = warp_sum(s);
            if (lane == 0) local += softplusf(s - MARGINF);
        }
        if (lane == 0) sh[wid] = local;
        __syncthreads();
        if (tid == 0) {
            float t = 0.f;
#pragma unroll
            for (int w = 0; w < 8; w++) t += sh[w];
            g_negsp[b] = t;
        }
    }
}

// ---------------------------------------------------------------------------
// Final combine + scalar reduce (double accumulation).
// ---------------------------------------------------------------------------
__global__ __launch_bounds__(512, 1) void final_kernel(float* __restrict__ out)
{
    __shared__ double sh[16];
    const int tid = threadIdx.x;
    double local = 0.0;
    for (int i = tid; i < BATCH; i += 512) {
        float pt = softplusf(g_dpos[i] - MARGINF);     // -log_sigmoid(M - d_pos)
        float nt = -g_negsp[i] * (1.f / NNEG);         // mean log_sigmoid(M - d_neg)
        local += (double)(g_conf[i] * (pt + nt));
    }
#pragma unroll
    for (int o = 16; o; o >>= 1) local += __shfl_xor_sync(0xffffffffu, local, o);
    const int lane = tid & 31, wid = tid >> 5;
    if (lane == 0) sh[wid] = local;
    __syncthreads();
    if (tid < 16) {
        double v = sh[tid];
#pragma unroll
        for (int o = 8; o; o >>= 1) v += __shfl_xor_sync(0x0000ffffu, v, o);
        if (tid == 0) out[0] = (float)v;
    }
}

// ---------------------------------------------------------------------------
extern "C" void kernel_launch(void* const* d_in, const int* in_sizes, int n_in,
                              void* d_out, int out_size)
{
    const int* pos = (const int*)d_in[0];
    const int* neg = (const int*)d_in[1];
    // negative_sample_size may or may not be materialized as input[2]
    const int o = (n_in >= 9) ? 1 : 0;
    const float* ent = (const float*)d_in[2 + o];
    const float* rel = (const float*)d_in[3 + o];
    const float* W1  = (const float*)d_in[4 + o];
    const float* b1  = (const float*)d_in[5 + o];
    const float* W2  = (const float*)d_in[6 + o];
    const float* b2  = (const float*)d_in[7 + o];
    float* out = (float*)d_out;

    fused_kernel<<<GRID_TOTAL, 256>>>(pos, neg, ent, rel, W1, b1, W2, b2);
    final_kernel<<<1, 512>>>(out);
}

// round 4
// speedup vs baseline: 1.0264x; 1.0264x over previous
#include <cuda_runtime.h>
#include <math.h>

#define BATCH 4096
#define NNEG 64
#define DIM 128
#define HID 512
#define HALF_HID 256
#define MARGINF 24.0f
#define MROWS 32                     // rows per MLP block

// Scratch (__device__ globals; written non-atomically each replay).
__device__ float g_part[2][BATCH];   // per-half logit partial sums
__device__ float g_dpos[BATCH];

__device__ __forceinline__ float warp_sum(float v) {
#pragma unroll
    for (int o = 16; o; o >>= 1) v += __shfl_xor_sync(0xffffffffu, v, o);
    return v;
}

__device__ __forceinline__ float softplusf(float z) {   // -log_sigmoid(-z)
    return fmaxf(z, 0.f) + log1pf(expf(-fabsf(z)));
}

__device__ __forceinline__ unsigned long long pack2(float x, float y) {
    unsigned long long r;
    asm("mov.b64 %0, {%1, %2};" : "=l"(r) : "f"(x), "f"(y));
    return r;
}
__device__ __forceinline__ void fma2(unsigned long long& d,
                                     unsigned long long a, unsigned long long b) {
    asm("fma.rn.f32x2 %0, %1, %2, %3;" : "=l"(d) : "l"(a), "l"(b), "l"(d));
}
__device__ __forceinline__ float2 unpack2(unsigned long long v) {
    float2 f;
    asm("mov.b64 {%0, %1}, %2;" : "=f"(f.x), "=f"(f.y) : "l"(v));
    return f;
}

// ---------------------------------------------------------------------------
// MLP kernel: grid = 128 row-tiles x 2 col-halves = 256 blocks, 256 threads.
// Thread tile 4 rows x 8 cols, packed f32x2 FMA (16 fma2 per k).
// Warp wid covers rows wid*4..+3 across all 32 col-groups of its half
// -> one warp_sum completes the half-dot per row.
// ---------------------------------------------------------------------------
__global__ __launch_bounds__(256) void mlp_kernel(
    const int* __restrict__ pos, const float* __restrict__ ent,
    const float* __restrict__ rel, const float* __restrict__ W1,
    const float* __restrict__ b1, const float* __restrict__ W2)
{
    __shared__ float shA[DIM][36];       // diff tile [k][row], 16B-aligned rows
    __shared__ int   sh_idx[MROWS][3];

    const int tid  = threadIdx.x;
    const int lane = tid & 31;
    const int wid  = tid >> 5;
    const int tile = blockIdx.x >> 1;
    const int half = blockIdx.x & 1;
    const int row0 = tile * MROWS;
    const int col0 = half * HALF_HID;

    if (tid < MROWS * 3)
        sh_idx[tid / 3][tid % 3] = pos[(row0 + tid / 3) * 3 + (tid % 3)];
    __syncthreads();

    // gather + diff (coalesced over k)
#pragma unroll
    for (int s = tid; s < MROWS * DIM; s += 256) {
        int row = s >> 7, k = s & 127;
        size_t h = (size_t)sh_idx[row][0];
        int    r = sh_idx[row][1];
        size_t t = (size_t)sh_idx[row][2];
        shA[k][row] = ent[h * DIM + k] + rel[(size_t)r * DIM + k] - ent[t * DIM + k];
    }
    __syncthreads();

    // d_pos (half 0 only): warp wid -> rows wid*4..+3
    if (half == 0) {
#pragma unroll
        for (int rr = 0; rr < 4; rr++) {
            int row = wid * 4 + rr;
            float s = 0.f;
#pragma unroll
            for (int kk = 0; kk < 4; kk++) s += fabsf(shA[lane + kk * 32][row]);
            s = warp_sum(s);
            if (lane == 0) g_dpos[row0 + row] = s;
        }
    }

    // GEMM: rows wid*4..+3, cols col0 + lane*8..+7
    const int rg = wid;
    const int cg = lane;
    unsigned long long acc2[4][4];
#pragma unroll
    for (int r = 0; r < 4; r++)
#pragma unroll
        for (int p = 0; p < 4; p++) acc2[r][p] = 0ull;

    const ulonglong2* Wp = (const ulonglong2*)(W1 + col0);  // row k = 128 ull2

#pragma unroll 8
    for (int k = 0; k < DIM; k++) {
        float4 a4 = *(const float4*)&shA[k][rg * 4];        // warp-broadcast LDS
        ulonglong2 w0 = __ldg(Wp + (size_t)k * 128 + cg * 2);
        ulonglong2 w1 = __ldg(Wp + (size_t)k * 128 + cg * 2 + 1);
        unsigned long long wv[4] = {w0.x, w0.y, w1.x, w1.y};
        unsigned long long ad[4] = {pack2(a4.x, a4.x), pack2(a4.y, a4.y),
                                    pack2(a4.z, a4.z), pack2(a4.w, a4.w)};
#pragma unroll
        for (int r = 0; r < 4; r++)
#pragma unroll
            for (int p = 0; p < 4; p++)
                fma2(acc2[r][p], ad[r], wv[p]);
    }

    // epilogue: relu(acc + b1) * W2, warp-reduce -> half-partial per row
    float4 b0 = __ldg((const float4*)(b1 + col0 + cg * 8));
    float4 b4 = __ldg((const float4*)(b1 + col0 + cg * 8 + 4));
    float4 v0 = __ldg((const float4*)(W2 + col0 + cg * 8));
    float4 v4 = __ldg((const float4*)(W2 + col0 + cg * 8 + 4));
    float bv[8]  = {b0.x, b0.y, b0.z, b0.w, b4.x, b4.y, b4.z, b4.w};
    float w2v[8] = {v0.x, v0.y, v0.z, v0.w, v4.x, v4.y, v4.z, v4.w};

#pragma unroll
    for (int r = 0; r < 4; r++) {
        float s = 0.f;
#pragma unroll
        for (int p = 0; p < 4; p++) {
            float2 u = unpack2(acc2[r][p]);
            s += fmaxf(u.x + bv[p * 2],     0.f) * w2v[p * 2];
            s += fmaxf(u.y + bv[p * 2 + 1], 0.f) * w2v[p * 2 + 1];
        }
        s = warp_sum(s);
        if (lane == 0) g_part[half][row0 + rg * 4 + r] = s;
    }
}

// ---------------------------------------------------------------------------
// Neg kernel + final fold. One block per batch row. 8 warps, 8 negs/warp,
// 2 negs per step (6 outstanding 512B gathers). Thread 0 combines conf,
// pos term, neg term and atomicAdds the contribution into out[0].
// ---------------------------------------------------------------------------
__global__ __launch_bounds__(256, 8) void neg_kernel(
    const int* __restrict__ negt, const float* __restrict__ ent,
    const float* __restrict__ rel, const float* __restrict__ b2,
    float* __restrict__ out)
{
    const int b    = blockIdx.x;
    const int lane = threadIdx.x & 31;
    const int wid  = threadIdx.x >> 5;
    __shared__ float sh[8];

    float local = 0.f;
#pragma unroll
    for (int u = 0; u < 4; u++) {
        int n0 = wid + u * 16;
        int n1 = n0 + 8;
        int base0 = (b * NNEG + n0) * 3;
        int base1 = (b * NNEG + n1) * 3;
        int h0 = __ldg(negt + base0), r0 = __ldg(negt + base0 + 1), t0 = __ldg(negt + base0 + 2);
        int h1 = __ldg(negt + base1), r1 = __ldg(negt + base1 + 1), t1 = __ldg(negt + base1 + 2);
        float4 a0 = __ldg((const float4*)(ent + (size_t)h0 * DIM) + lane);
        float4 c0 = __ldg((const float4*)(ent + (size_t)t0 * DIM) + lane);
        float4 a1 = __ldg((const float4*)(ent + (size_t)h1 * DIM) + lane);
        float4 c1 = __ldg((const float4*)(ent + (size_t)t1 * DIM) + lane);
        float4 q0 = __ldg((const float4*)(rel + (size_t)r0 * DIM) + lane);
        float4 q1 = __ldg((const float4*)(rel + (size_t)r1 * DIM) + lane);
        float s0 = fabsf(a0.x + q0.x - c0.x) + fabsf(a0.y + q0.y - c0.y)
                 + fabsf(a0.z + q0.z - c0.z) + fabsf(a0.w + q0.w - c0.w);
        float s1 = fabsf(a1.x + q1.x - c1.x) + fabsf(a1.y + q1.y - c1.y)
                 + fabsf(a1.z + q1.z - c1.z) + fabsf(a1.w + q1.w - c1.w);
        s0 = warp_sum(s0);
        s1 = warp_sum(s1);
        if (lane == 0)
            local += softplusf(s0 - MARGINF) + softplusf(s1 - MARGINF);
    }
    if (lane == 0) sh[wid] = local;
    __syncthreads();
    if (threadIdx.x == 0) {
        float negsp = 0.f;
#pragma unroll
        for (int w = 0; w < 8; w++) negsp += sh[w];
        float logit = b2[0] + g_part[0][b] + g_part[1][b];
        float conf  = 1.f / (1.f + expf(-logit));
        float pt    = softplusf(g_dpos[b] - MARGINF);
        atomicAdd(out, conf * (pt - negsp * (1.f / NNEG)));
    }
}

__global__ void zero_kernel(float* __restrict__ out) { out[0] = 0.f; }

// ---------------------------------------------------------------------------
extern "C" void kernel_launch(void* const* d_in, const int* in_sizes, int n_in,
                              void* d_out, int out_size)
{
    const int* pos = (const int*)d_in[0];
    const int* neg = (const int*)d_in[1];
    const int o = (n_in >= 9) ? 1 : 0;   // negative_sample_size scalar slot
    const float* ent = (const float*)d_in[2 + o];
    const float* rel = (const float*)d_in[3 + o];
    const float* W1  = (const float*)d_in[4 + o];
    const float* b1  = (const float*)d_in[5 + o];
    const float* W2  = (const float*)d_in[6 + o];
    const float* b2  = (const float*)d_in[7 + o];
    float* out = (float*)d_out;

    zero_kernel<<<1, 1>>>(out);
    mlp_kernel<<<256, 256>>>(pos, ent, rel, W1, b1, W2);
    neg_kernel<<<BATCH, 256>>>(neg, ent, rel, b2, out);
}

// round 5
// speedup vs baseline: 1.2860x; 1.2529x over previous
#include <cuda_runtime.h>
#include <math.h>

#define BATCH 4096
#define NNEG 64
#define DIM 128
#define HID 512
#define MARGINF 24.0f
#define MROWS 32

// Scratch (__device__ globals; overwritten every replay, no zeroing needed).
__device__ float g_conf[BATCH];
__device__ float g_dpos[BATCH];
__device__ float g_negsp[BATCH];

__device__ __forceinline__ float warp_sum(float v) {
#pragma unroll
    for (int o = 16; o; o >>= 1) v += __shfl_xor_sync(0xffffffffu, v, o);
    return v;
}

// stable softplus(z) = max(z,0) + log1p(exp(-|z|));  -log_sigmoid(x) = softplus(-x)
__device__ __forceinline__ float softplusf(float z) {
    return fmaxf(z, 0.f) + log1pf(expf(-fabsf(z)));
}

// ---------------------------------------------------------------------------
// MLP / positive kernel (R1-proven version). 32 rows/block, 512 threads,
// thread tile 4 rows x 8 cols reading W1 straight from L2 (coalesced LDG),
// A tile broadcast from shared. Also zeroes out[0] (block 0) so the final
// kernel can atomicAdd after the join.
// ---------------------------------------------------------------------------
__global__ __launch_bounds__(512, 1) void mlp_pos_kernel(
    const int* __restrict__ pos, const float* __restrict__ ent,
    const float* __restrict__ rel, const float* __restrict__ W1,
    const float* __restrict__ b1, const float* __restrict__ W2,
    const float* __restrict__ b2, float* __restrict__ out)
{
    __shared__ float shT[DIM][36];      // [k][row], pitch 36 -> 16B-aligned rows
    __shared__ int   sh_idx[MROWS][3];
    __shared__ float sh_part[16][MROWS];

    const int tid  = threadIdx.x;
    const int lane = tid & 31;
    const int wid  = tid >> 5;
    const int row0 = blockIdx.x * MROWS;

    if (blockIdx.x == 0 && tid == 0) out[0] = 0.f;

    if (tid < MROWS * 3)
        sh_idx[tid / 3][tid % 3] = pos[(row0 + tid / 3) * 3 + (tid % 3)];
    __syncthreads();

    // gather + diff: consecutive tid -> consecutive k (coalesced 512B per row)
#pragma unroll
    for (int s = tid; s < MROWS * DIM; s += 512) {
        int row = s >> 7, k = s & 127;
        size_t h = (size_t)sh_idx[row][0];
        int    r = sh_idx[row][1];
        size_t t = (size_t)sh_idx[row][2];
        shT[k][row] = ent[h * DIM + k] + rel[(size_t)r * DIM + k] - ent[t * DIM + k];
    }
    __syncthreads();

    // d_pos: warp w handles rows 2w, 2w+1
#pragma unroll
    for (int rr = 0; rr < 2; rr++) {
        int row = wid * 2 + rr;
        float s = 0.f;
#pragma unroll
        for (int kk = 0; kk < 4; kk++) s += fabsf(shT[lane + kk * 32][row]);
        s = warp_sum(s);
        if (lane == 0) g_dpos[row0 + row] = s;
    }

    // GEMM: column j = tid, 32 row-accumulators
    float acc[MROWS];
#pragma unroll
    for (int r = 0; r < MROWS; r++) acc[r] = 0.f;
    const int j = tid;

#pragma unroll 4
    for (int k = 0; k < DIM; k++) {
        float w = W1[k * HID + j];
#pragma unroll
        for (int q = 0; q < MROWS / 4; q++) {
            float4 d4 = *(const float4*)&shT[k][q * 4];   // broadcast LDS.128
            acc[q * 4 + 0] = fmaf(d4.x, w, acc[q * 4 + 0]);
            acc[q * 4 + 1] = fmaf(d4.y, w, acc[q * 4 + 1]);
            acc[q * 4 + 2] = fmaf(d4.z, w, acc[q * 4 + 2]);
            acc[q * 4 + 3] = fmaf(d4.w, w, acc[q * 4 + 3]);
        }
    }

    const float bj = b1[j], w2 = W2[j];
#pragma unroll
    for (int r = 0; r < MROWS; r++) acc[r] = fmaxf(acc[r] + bj, 0.f) * w2;

    // reduce 512 threads -> 1 logit per row
#pragma unroll
    for (int r = 0; r < MROWS; r++) {
        float v = warp_sum(acc[r]);
        if (lane == 0) sh_part[wid][r] = v;
    }
    __syncthreads();
    if (tid < MROWS) {
        float s = b2[0];
#pragma unroll
        for (int w = 0; w < 16; w++) s += sh_part[w][tid];
        g_conf[row0 + tid] = 1.f / (1.f + expf(-s));
    }
}

// ---------------------------------------------------------------------------
// Negative kernel (R1-proven). One block per batch row, 8 warps, 8 negs/warp.
// One warp per triple: 32 lanes x float4 = coalesced 512B row gathers.
// ---------------------------------------------------------------------------
__global__ __launch_bounds__(256, 8) void neg_kernel(
    const int* __restrict__ negt, const float* __restrict__ ent,
    const float* __restrict__ rel)
{
    const int b    = blockIdx.x;
    const int lane = threadIdx.x & 31;
    const int wid  = threadIdx.x >> 5;
    __shared__ float sh[8];

    float local = 0.f;
#pragma unroll
    for (int n = wid; n < NNEG; n += 8) {
        int base = (b * NNEG + n) * 3;
        int hi = __ldg(negt + base);
        int ri = __ldg(negt + base + 1);
        int ti = __ldg(negt + base + 2);
        float4 a  = __ldg((const float4*)(ent + (size_t)hi * DIM) + lane);
        float4 rr = __ldg((const float4*)(rel + (size_t)ri * DIM) + lane);
        float4 c  = __ldg((const float4*)(ent + (size_t)ti * DIM) + lane);
        float s = fabsf(a.x + rr.x - c.x) + fabsf(a.y + rr.y - c.y)
                + fabsf(a.z + rr.z - c.z) + fabsf(a.w + rr.w - c.w);
        s = warp_sum(s);
        if (lane == 0) local += softplusf(s - MARGINF);
    }
    if (lane == 0) sh[wid] = local;
    __syncthreads();
    if (threadIdx.x == 0) {
        float t = 0.f;
#pragma unroll
        for (int w = 0; w < 8; w++) t += sh[w];
        g_negsp[b] = t;
    }
}

// ---------------------------------------------------------------------------
// Final combine: 8 blocks x 512 threads, one batch row per thread,
// block-reduce (double), atomicAdd partial into out[0] (zeroed by mlp kernel).
// ---------------------------------------------------------------------------
__global__ __launch_bounds__(512, 2) void final_kernel(float* __restrict__ out)
{
    __shared__ double sh[16];
    const int tid = threadIdx.x;
    const int i = blockIdx.x * 512 + tid;

    float pt = softplusf(g_dpos[i] - MARGINF);       // -log_sigmoid(M - d_pos)
    float nt = -g_negsp[i] * (1.f / NNEG);           // mean log_sigmoid(M - d_neg)
    double local = (double)(g_conf[i] * (pt + nt));

#pragma unroll
    for (int o = 16; o; o >>= 1) local += __shfl_xor_sync(0xffffffffu, local, o);
    const int lane = tid & 31, wid = tid >> 5;
    if (lane == 0) sh[wid] = local;
    __syncthreads();
    if (tid < 16) {
        double v = sh[tid];
#pragma unroll
        for (int o = 8; o; o >>= 1) v += __shfl_xor_sync(0x0000ffffu, v, o);
        if (tid == 0) atomicAdd(out, (float)v);
    }
}

// ---------------------------------------------------------------------------
// Fork/join: mlp on a non-blocking side stream overlaps the DRAM-bound neg
// kernel on the (captured) default stream. Events make this capture-legal.
// ---------------------------------------------------------------------------
extern "C" void kernel_launch(void* const* d_in, const int* in_sizes, int n_in,
                              void* d_out, int out_size)
{
    static cudaStream_t s2 = nullptr;
    static cudaEvent_t evFork = nullptr, evJoin = nullptr;
    if (s2 == nullptr) {
        cudaStreamCreateWithFlags(&s2, cudaStreamNonBlocking);
        cudaEventCreateWithFlags(&evFork, cudaEventDisableTiming);
        cudaEventCreateWithFlags(&evJoin, cudaEventDisableTiming);
    }

    const int* pos = (const int*)d_in[0];
    const int* neg = (const int*)d_in[1];
    const int o = (n_in >= 9) ? 1 : 0;   // negative_sample_size scalar slot
    const float* ent = (const float*)d_in[2 + o];
    const float* rel = (const float*)d_in[3 + o];
    const float* W1  = (const float*)d_in[4 + o];
    const float* b1  = (const float*)d_in[5 + o];
    const float* W2  = (const float*)d_in[6 + o];
    const float* b2  = (const float*)d_in[7 + o];
    float* out = (float*)d_out;

    // fork: side stream inherits capture via event wait
    cudaEventRecord(evFork, 0);
    cudaStreamWaitEvent(s2, evFork, 0);

    mlp_pos_kernel<<<BATCH / MROWS, 512, 0, s2>>>(pos, ent, rel, W1, b1, W2, b2, out);
    cudaEventRecord(evJoin, s2);

    neg_kernel<<<BATCH, 256>>>(neg, ent, rel);   // overlaps mlp

    // join, then combine
    cudaStreamWaitEvent(0, evJoin, 0);
    final_kernel<<<8, 512>>>(out);
}